// round 2
// baseline (speedup 1.0000x reference)
#include <cuda_runtime.h>
#include <stdint.h>
#include <math.h>

#define N_ROWS 16384
#define K_EMB  8192
#define D_EMB  64
#define TOPK   10

#define BR          64              // rows per block
#define THREADS_M   128             // 2 K-halves x 64 rows
#define HALF_K      (K_EMB/2)       // 4096
#define TILE        64              // codewords per smem tile (per half)
#define NTILES      (HALF_K/TILE)   // 64
#define GRID_MAIN   (N_ROWS/BR)     // 256

// output layout (float32, concatenated in reference return order)
#define OFF_LOSS  1048576
#define OFF_IDX   (OFF_LOSS + 1)
#define OFF_MIND  (OFF_IDX + N_ROWS)
#define OFF_PERP  (OFF_MIND + N_ROWS)

// device scratch (no allocations allowed)
__device__ float g_esq[K_EMB];
__device__ int   g_counts[K_EMB];
__device__ float g_losspart[GRID_MAIN];
__device__ float g_validpart[GRID_MAIN];

__device__ __forceinline__ void ffma2(uint64_t &acc, uint64_t a, uint64_t b) {
    asm("fma.rn.f32x2 %0, %1, %2, %0;" : "+l"(acc) : "l"(a), "l"(b));
}
__device__ __forceinline__ float2 u2f(uint64_t v) {
    float2 f; asm("mov.b64 {%0,%1}, %2;" : "=f"(f.x), "=f"(f.y) : "l"(v)); return f;
}

// ---------------------------------------------------------------------------
// prep: per-codeword squared norms + zero histogram
// ---------------------------------------------------------------------------
__global__ void vq_prep(const float* __restrict__ cb) {
    int k = blockIdx.x * blockDim.x + threadIdx.x;
    if (k < K_EMB) {
        const float* e = cb + (size_t)k * D_EMB;
        float s = 0.f;
        #pragma unroll
        for (int i = 0; i < D_EMB; i++) s = fmaf(e[i], e[i], s);
        g_esq[k] = s;
        g_counts[k] = 0;
    }
}

// ---------------------------------------------------------------------------
// main: distances + per-row top-10 + gumbel sample + outputs + partial losses
// thread (half, r): scans codewords [half*4096, half*4096+4096) for row r.
// warp = 32 rows, same half -> all lanes read the SAME codeword (smem broadcast)
// ---------------------------------------------------------------------------
__global__ __launch_bounds__(THREADS_M) void vq_main(
    const float* __restrict__ inp, const float* __restrict__ cb,
    const float* __restrict__ gum, float* __restrict__ out)
{
    __shared__ float s_cb[2][TILE][D_EMB];   // 32 KB
    __shared__ float s_esq[2][TILE];
    __shared__ float s_d[2][BR][TOPK];
    __shared__ int   s_i[2][BR][TOPK];
    __shared__ float s_redA[THREADS_M];
    __shared__ float s_redB[THREADS_M];

    const int tid  = threadIdx.x;
    const int half = tid >> 6;
    const int r    = tid & 63;
    const int row  = blockIdx.x * BR + r;

    // row x in registers (packed f32x2)
    uint64_t xp[32];
    const uint64_t* xrow = reinterpret_cast<const uint64_t*>(inp + (size_t)row * D_EMB);
    #pragma unroll
    for (int i = 0; i < 32; i++) xp[i] = xrow[i];
    float xsq = 0.f;
    #pragma unroll
    for (int i = 0; i < 32; i++) {
        float2 f = u2f(xp[i]);
        xsq = fmaf(f.x, f.x, xsq);
        xsq = fmaf(f.y, f.y, xsq);
    }

    float td[TOPK]; int ti[TOPK];
    #pragma unroll
    for (int j = 0; j < TOPK; j++) { td[j] = __int_as_float(0x7f800000); ti[j] = 0; }

    const int kbase0 = half * HALF_K;
    const float4* gcb4 = reinterpret_cast<const float4*>(cb);

    for (int t = 0; t < NTILES; ++t) {
        __syncthreads();
        // cooperative tile load: 2 halves x 64 codewords x 64 floats = 2048 float4
        const int kb = t * TILE;
        #pragma unroll
        for (int it = 0; it < 16; ++it) {
            int li  = tid + THREADS_M * it;     // 0..2047
            int hl  = li >> 10;
            int rem = li & 1023;
            int cw  = rem >> 4;
            int col = rem & 15;
            float4 v = gcb4[((size_t)(hl * HALF_K + kb + cw)) * 16 + col];
            reinterpret_cast<float4*>(&s_cb[hl][cw][0])[col] = v;
        }
        if (tid < 2 * TILE) {
            int hl = tid >> 6, cw = tid & 63;
            s_esq[hl][cw] = g_esq[hl * HALF_K + kb + cw];
        }
        __syncthreads();

        #pragma unroll 2
        for (int c = 0; c < TILE; ++c) {
            uint64_t a0 = 0, a1 = 0, a2 = 0, a3 = 0;
            const ulonglong2* p = reinterpret_cast<const ulonglong2*>(&s_cb[half][c][0]);
            #pragma unroll
            for (int i = 0; i < 8; i++) {
                ulonglong2 v0 = p[2 * i];
                ulonglong2 v1 = p[2 * i + 1];
                ffma2(a0, xp[4 * i + 0], v0.x);
                ffma2(a1, xp[4 * i + 1], v0.y);
                ffma2(a2, xp[4 * i + 2], v1.x);
                ffma2(a3, xp[4 * i + 3], v1.y);
            }
            float2 f0 = u2f(a0), f1 = u2f(a1), f2 = u2f(a2), f3 = u2f(a3);
            float dot = ((f0.x + f0.y) + (f1.x + f1.y)) + ((f2.x + f2.y) + (f3.x + f3.y));
            // match reference: (xsq + esq) - 2*dot
            float dval = (xsq + s_esq[half][c]) - 2.0f * dot;
            if (dval < td[TOPK - 1]) {                // strict <: stable tie-break by index
                td[TOPK - 1] = dval;
                ti[TOPK - 1] = kbase0 + kb + c;
                #pragma unroll
                for (int j = TOPK - 1; j > 0; --j) {
                    if (td[j] < td[j - 1]) {
                        float tf = td[j]; td[j] = td[j - 1]; td[j - 1] = tf;
                        int   tg = ti[j]; ti[j] = ti[j - 1]; ti[j - 1] = tg;
                    } else break;
                }
            }
        }
    }

    __syncthreads();
    #pragma unroll
    for (int j = 0; j < TOPK; j++) { s_d[half][r][j] = td[j]; s_i[half][r][j] = ti[j]; }
    __syncthreads();

    float sumsq = 0.f, vflag = 0.f;
    if (half == 0) {
        // merge the two sorted halves (ties -> half 0 = lower global index)
        float md[TOPK]; int mi[TOPK];
        int i0 = 0, i1 = 0;
        #pragma unroll
        for (int j = 0; j < TOPK; j++) {
            float d0 = s_d[0][r][i0], d1 = s_d[1][r][i1];
            if (d0 <= d1) { md[j] = d0; mi[j] = s_i[0][r][i0]; i0++; }
            else          { md[j] = d1; mi[j] = s_i[1][r][i1]; i1++; }
        }
        // gumbel-max over top-k slots (argmax keeps first on ties -> strict >)
        const float* g = gum + (size_t)row * TOPK;
        float best = g[0] - md[0]; int jbest = 0;
        #pragma unroll
        for (int j = 1; j < TOPK; j++) {
            float v = g[j] - md[j];
            if (v > best) { best = v; jbest = j; }
        }
        int   idx  = mi[jbest];
        float mind = md[jbest];
        bool  valid = (xsq > 1e-12f);     // norm > 1e-6
        float vm = valid ? 1.0f : 0.0f;

        // quantized_st row = x + ((q*vm) - x)   (match reference ST arithmetic)
        const float4* q4 = reinterpret_cast<const float4*>(cb + (size_t)idx * D_EMB);
        float4* o4 = reinterpret_cast<float4*>(out + (size_t)row * D_EMB);
        #pragma unroll
        for (int i = 0; i < 16; i++) {
            float4 q = q4[i];
            float2 xa = u2f(xp[2 * i]);
            float2 xb = u2f(xp[2 * i + 1]);
            float d0 = q.x - xa.x, d1 = q.y - xa.y, d2 = q.z - xb.x, d3 = q.w - xb.y;
            sumsq = fmaf(d0, d0, sumsq); sumsq = fmaf(d1, d1, sumsq);
            sumsq = fmaf(d2, d2, sumsq); sumsq = fmaf(d3, d3, sumsq);
            float4 qo;
            qo.x = xa.x + (q.x * vm - xa.x);
            qo.y = xa.y + (q.y * vm - xa.y);
            qo.z = xb.x + (q.z * vm - xb.x);
            qo.w = xb.y + (q.w * vm - xb.y);
            o4[i] = qo;
        }
        sumsq *= vm;
        vflag  = vm;
        out[OFF_IDX  + row] = valid ? (float)idx : 0.0f;
        out[OFF_MIND + row] = valid ? mind : 0.0f;
        if (valid) atomicAdd(&g_counts[idx], 1);
    }

    // deterministic block partials (fixed tree)
    s_redA[tid] = sumsq; s_redB[tid] = vflag;
    __syncthreads();
    for (int st = THREADS_M / 2; st > 0; st >>= 1) {
        if (tid < st) { s_redA[tid] += s_redA[tid + st]; s_redB[tid] += s_redB[tid + st]; }
        __syncthreads();
    }
    if (tid == 0) { g_losspart[blockIdx.x] = s_redA[0]; g_validpart[blockIdx.x] = s_redB[0]; }
}

// ---------------------------------------------------------------------------
// final: deterministic reductions -> total_loss, perplexity
// ---------------------------------------------------------------------------
__global__ void vq_final(float* __restrict__ out) {
    __shared__ float sA[256], sB[256];
    int tid = threadIdx.x;
    sA[tid] = g_losspart[tid];     // GRID_MAIN == 256
    sB[tid] = g_validpart[tid];
    __syncthreads();
    for (int st = 128; st > 0; st >>= 1) {
        if (tid < st) { sA[tid] += sA[tid + st]; sB[tid] += sB[tid + st]; }
        __syncthreads();
    }
    float n_valid = fmaxf(sB[0], 1.0f);
    float loss_vq = sA[0] / (n_valid * (float)D_EMB);
    __syncthreads();

    float local = 0.f;
    for (int k = tid; k < K_EMB; k += 256) {
        float p = (float)g_counts[k] / n_valid;
        local += p * logf(p + 1e-10f);
    }
    sA[tid] = local;
    __syncthreads();
    for (int st = 128; st > 0; st >>= 1) {
        if (tid < st) sA[tid] += sA[tid + st];
        __syncthreads();
    }
    if (tid == 0) {
        float perplexity = expf(-sA[0]);
        float ploss = -logf(perplexity + 1e-10f);
        out[OFF_LOSS] = loss_vq + 0.01f * ploss;
        out[OFF_PERP] = perplexity;
    }
}

extern "C" void kernel_launch(void* const* d_in, const int* in_sizes, int n_in,
                              void* d_out, int out_size) {
    (void)in_sizes; (void)n_in; (void)out_size;
    const float* inp = (const float*)d_in[0];
    const float* cb  = (const float*)d_in[1];
    const float* gum = (const float*)d_in[2];
    float* out = (float*)d_out;

    vq_prep<<<K_EMB / 256, 256>>>(cb);
    vq_main<<<GRID_MAIN, THREADS_M>>>(inp, cb, gum, out);
    vq_final<<<1, 256>>>(out);
}

// round 5
// speedup vs baseline: 1.0312x; 1.0312x over previous
#include <cuda_runtime.h>
#include <stdint.h>
#include <math.h>

#define N_ROWS 16384
#define K_EMB  8192
#define D_EMB  64
#define TOPK   10

#define BR          64              // rows per block
#define THREADS_M   256             // 4 K-quarters x 64 rows
#define QUARTS      4
#define QK          (K_EMB/QUARTS)  // 2048 codewords per thread
#define TILE        32              // codewords per smem tile (per quarter)
#define NTILES      (QK/TILE)       // 64
#define GRID_MAIN   (N_ROWS/BR)     // 256

// output layout (float32, concatenated in reference return order)
#define OFF_LOSS  1048576
#define OFF_IDX   (OFF_LOSS + 1)
#define OFF_MIND  (OFF_IDX + N_ROWS)
#define OFF_PERP  (OFF_MIND + N_ROWS)

// device scratch (no allocations allowed)
__device__ float g_esq[K_EMB];
__device__ int   g_counts[K_EMB];
__device__ float g_losspart[GRID_MAIN];
__device__ float g_validpart[GRID_MAIN];

__device__ __forceinline__ void ffma2(uint64_t &acc, uint64_t a, uint64_t b) {
    asm("fma.rn.f32x2 %0, %1, %2, %0;" : "+l"(acc) : "l"(a), "l"(b));
}
__device__ __forceinline__ uint64_t addf2(uint64_t a, uint64_t b) {
    uint64_t o; asm("add.rn.f32x2 %0, %1, %2;" : "=l"(o) : "l"(a), "l"(b)); return o;
}
__device__ __forceinline__ uint64_t mulf2(uint64_t a, uint64_t b) {
    uint64_t o; asm("mul.rn.f32x2 %0, %1, %2;" : "=l"(o) : "l"(a), "l"(b)); return o;
}
__device__ __forceinline__ float2 u2f(uint64_t v) {
    float2 f; asm("mov.b64 {%0,%1}, %2;" : "=f"(f.x), "=f"(f.y) : "l"(v)); return f;
}

// ---------------------------------------------------------------------------
// prep: per-codeword squared norms (coalesced, 8 lanes/codeword) + zero hist
// grid 256 x 256 threads; 32 codewords per block
// ---------------------------------------------------------------------------
__global__ __launch_bounds__(256) void vq_prep(const float* __restrict__ cb) {
    int k = blockIdx.x * 32 + (threadIdx.x >> 3);
    int l = threadIdx.x & 7;
    const float4* e4 = reinterpret_cast<const float4*>(cb + (size_t)k * D_EMB);
    float4 a = e4[l * 2], b = e4[l * 2 + 1];
    float s = 0.f;
    s = fmaf(a.x, a.x, s); s = fmaf(a.y, a.y, s);
    s = fmaf(a.z, a.z, s); s = fmaf(a.w, a.w, s);
    s = fmaf(b.x, b.x, s); s = fmaf(b.y, b.y, s);
    s = fmaf(b.z, b.z, s); s = fmaf(b.w, b.w, s);
    s += __shfl_xor_sync(0xffffffffu, s, 1);
    s += __shfl_xor_sync(0xffffffffu, s, 2);
    s += __shfl_xor_sync(0xffffffffu, s, 4);
    if (l == 0) g_esq[k] = s;
    if (threadIdx.x < 32) g_counts[blockIdx.x * 32 + threadIdx.x] = 0;
}

// ---------------------------------------------------------------------------
// main: distances + per-row top-10 + gumbel sample + outputs + partial losses
// thread (quart, r): scans codewords [quart*2048, quart*2048+2048) for row r.
// warp = 32 rows, same quarter -> all lanes read the SAME codeword (broadcast)
// ---------------------------------------------------------------------------
__global__ __launch_bounds__(THREADS_M, 2) void vq_main(
    const float* __restrict__ inp, const float* __restrict__ cb,
    const float* __restrict__ gum, float* __restrict__ out)
{
    // 32KB tile buffer; after the scan it is re-used for the top-k lists
    __shared__ __align__(16) unsigned char s_buf[QUARTS * TILE * D_EMB * 4];
    __shared__ float s_esq[QUARTS][TILE];
    __shared__ float s_redA[THREADS_M];
    __shared__ float s_redB[THREADS_M];

    float*  s_cb  = reinterpret_cast<float*>(s_buf);
    float4* s_cb4 = reinterpret_cast<float4*>(s_buf);
    float*  s_d   = reinterpret_cast<float*>(s_buf);                            // [4][64][10]
    int*    s_i   = reinterpret_cast<int*>(s_buf + QUARTS * BR * TOPK * 4);     // [4][64][10]

    const int tid   = threadIdx.x;
    const int quart = tid >> 6;
    const int r     = tid & 63;
    const int row   = blockIdx.x * BR + r;

    // row x in registers (packed f32x2), then fold -2 in: xm2 = -2*x
    uint64_t xp[32];
    const ulonglong2* xrow = reinterpret_cast<const ulonglong2*>(inp + (size_t)row * D_EMB);
    #pragma unroll
    for (int i = 0; i < 16; i++) { ulonglong2 v = xrow[i]; xp[2*i] = v.x; xp[2*i+1] = v.y; }
    float xsq = 0.f;
    #pragma unroll
    for (int i = 0; i < 32; i++) {
        float2 f = u2f(xp[i]);
        xsq = fmaf(f.x, f.x, xsq);
        xsq = fmaf(f.y, f.y, xsq);
    }
    uint64_t m2; asm("mov.b64 %0, {%1,%2};" : "=l"(m2) : "f"(-2.0f), "f"(-2.0f));
    #pragma unroll
    for (int i = 0; i < 32; i++) xp[i] = mulf2(xp[i], m2);

    float td[TOPK]; int ti[TOPK];
    #pragma unroll
    for (int j = 0; j < TOPK; j++) { td[j] = __int_as_float(0x7f800000); ti[j] = 0; }

    const int kbase = quart * QK;
    const float4* gcb4 = reinterpret_cast<const float4*>(cb);
    const float* esq_q = &s_esq[quart][0];
    const float* cb_q  = s_cb + quart * TILE * D_EMB;

    for (int t = 0; t < NTILES; ++t) {
        __syncthreads();
        const int kb = t * TILE;
        // cooperative tile load: 4 quarters x 32 codewords x 16 float4 = 2048
        #pragma unroll
        for (int it = 0; it < 8; ++it) {
            int li  = tid + THREADS_M * it;     // 0..2047
            int qq  = li >> 9;
            int rem = li & 511;
            int cw  = rem >> 4;
            int col = rem & 15;
            s_cb4[(qq * TILE + cw) * 16 + col] =
                gcb4[((size_t)(qq * QK + kb + cw)) * 16 + col];
        }
        if (tid < QUARTS * TILE) {
            int qq = tid >> 5, cw = tid & 31;
            s_esq[qq][cw] = g_esq[qq * QK + kb + cw];
        }
        __syncthreads();

        #pragma unroll 2
        for (int c = 0; c < TILE; ++c) {
            uint64_t a0 = 0, a1 = 0;
            const ulonglong2* p = reinterpret_cast<const ulonglong2*>(cb_q + c * D_EMB);
            #pragma unroll
            for (int i = 0; i < 16; i++) {
                ulonglong2 v = p[i];
                ffma2(a0, xp[2 * i],     v.x);
                ffma2(a1, xp[2 * i + 1], v.y);
            }
            float2 f = u2f(addf2(a0, a1));
            float dval = (xsq + esq_q[c]) + (f.x + f.y);   // ||x||^2 + ||e||^2 - 2 x.e
            if (dval < td[TOPK - 1]) {                     // strict <: stable tie-break
                td[TOPK - 1] = dval;
                ti[TOPK - 1] = kbase + kb + c;
                #pragma unroll
                for (int j = TOPK - 1; j > 0; --j) {
                    if (td[j] < td[j - 1]) {
                        float tf = td[j]; td[j] = td[j - 1]; td[j - 1] = tf;
                        int   tg = ti[j]; ti[j] = ti[j - 1]; ti[j - 1] = tg;
                    } else break;
                }
            }
        }
    }

    __syncthreads();   // tile buffer dead -> reuse for lists
    #pragma unroll
    for (int j = 0; j < TOPK; j++) {
        s_d[(quart * BR + r) * TOPK + j] = td[j];
        s_i[(quart * BR + r) * TOPK + j] = ti[j];
    }
    __syncthreads();

    float sumsq = 0.f, vflag = 0.f;
    if (quart == 0) {
        // merge 4 sorted lists; ties -> lower quarter (= lower global index)
        const float* L0 = &s_d[(0 * BR + r) * TOPK]; const int* I0 = &s_i[(0 * BR + r) * TOPK];
        const float* L1 = &s_d[(1 * BR + r) * TOPK]; const int* I1 = &s_i[(1 * BR + r) * TOPK];
        const float* L2 = &s_d[(2 * BR + r) * TOPK]; const int* I2 = &s_i[(2 * BR + r) * TOPK];
        const float* L3 = &s_d[(3 * BR + r) * TOPK]; const int* I3 = &s_i[(3 * BR + r) * TOPK];

        float mA[TOPK]; int iA[TOPK];
        float mB[TOPK]; int iB[TOPK];
        float md[TOPK]; int mi[TOPK];
        { int i0 = 0, i1 = 0;
          #pragma unroll
          for (int j = 0; j < TOPK; j++) {
              float d0 = L0[i0], d1 = L1[i1];
              if (d0 <= d1) { mA[j] = d0; iA[j] = I0[i0]; i0++; }
              else          { mA[j] = d1; iA[j] = I1[i1]; i1++; } } }
        { int i0 = 0, i1 = 0;
          #pragma unroll
          for (int j = 0; j < TOPK; j++) {
              float d0 = L2[i0], d1 = L3[i1];
              if (d0 <= d1) { mB[j] = d0; iB[j] = I2[i0]; i0++; }
              else          { mB[j] = d1; iB[j] = I3[i1]; i1++; } } }
        { int i0 = 0, i1 = 0;
          #pragma unroll
          for (int j = 0; j < TOPK; j++) {
              float d0 = mA[i0], d1 = mB[i1];
              if (d0 <= d1) { md[j] = d0; mi[j] = iA[i0]; i0++; }
              else          { md[j] = d1; mi[j] = iB[i1]; i1++; } } }

        // gumbel-max over top-k slots (argmax keeps first on ties -> strict >)
        const float* g = gum + (size_t)row * TOPK;
        float best = g[0] - md[0]; int jbest = 0;
        #pragma unroll
        for (int j = 1; j < TOPK; j++) {
            float v = g[j] - md[j];
            if (v > best) { best = v; jbest = j; }
        }
        int   idx  = mi[jbest];
        float mind = md[jbest];
        bool  valid = (xsq > 1e-12f);     // norm > 1e-6
        float vm = valid ? 1.0f : 0.0f;

        // quantized_st row = x + ((q*vm) - x)   (match reference ST arithmetic)
        const float4* q4  = reinterpret_cast<const float4*>(cb  + (size_t)idx * D_EMB);
        const float4* xr4 = reinterpret_cast<const float4*>(inp + (size_t)row * D_EMB);
        float4* o4 = reinterpret_cast<float4*>(out + (size_t)row * D_EMB);
        #pragma unroll
        for (int i = 0; i < 16; i++) {
            float4 q = q4[i];
            float4 x = xr4[i];
            float d0 = q.x - x.x, d1 = q.y - x.y, d2 = q.z - x.z, d3 = q.w - x.w;
            sumsq = fmaf(d0, d0, sumsq); sumsq = fmaf(d1, d1, sumsq);
            sumsq = fmaf(d2, d2, sumsq); sumsq = fmaf(d3, d3, sumsq);
            float4 qo;
            qo.x = x.x + (q.x * vm - x.x);
            qo.y = x.y + (q.y * vm - x.y);
            qo.z = x.z + (q.z * vm - x.z);
            qo.w = x.w + (q.w * vm - x.w);
            o4[i] = qo;
        }
        sumsq *= vm;
        vflag  = vm;
        out[OFF_IDX  + row] = valid ? (float)idx : 0.0f;
        out[OFF_MIND + row] = valid ? mind : 0.0f;
        if (valid) atomicAdd(&g_counts[idx], 1);
    }

    // deterministic block partials (fixed tree)
    s_redA[tid] = sumsq; s_redB[tid] = vflag;
    __syncthreads();
    for (int st = THREADS_M / 2; st > 0; st >>= 1) {
        if (tid < st) { s_redA[tid] += s_redA[tid + st]; s_redB[tid] += s_redB[tid + st]; }
        __syncthreads();
    }
    if (tid == 0) { g_losspart[blockIdx.x] = s_redA[0]; g_validpart[blockIdx.x] = s_redB[0]; }
}

// ---------------------------------------------------------------------------
// final: deterministic reductions -> total_loss, perplexity
// ---------------------------------------------------------------------------
__global__ void vq_final(float* __restrict__ out) {
    __shared__ float sA[256], sB[256];
    int tid = threadIdx.x;
    sA[tid] = g_losspart[tid];     // GRID_MAIN == 256
    sB[tid] = g_validpart[tid];
    __syncthreads();
    for (int st = 128; st > 0; st >>= 1) {
        if (tid < st) { sA[tid] += sA[tid + st]; sB[tid] += sB[tid + st]; }
        __syncthreads();
    }
    float n_valid = fmaxf(sB[0], 1.0f);
    float loss_vq = sA[0] / (n_valid * (float)D_EMB);
    __syncthreads();

    float local = 0.f;
    for (int k = tid; k < K_EMB; k += 256) {
        float p = (float)g_counts[k] / n_valid;
        local += p * logf(p + 1e-10f);
    }
    sA[tid] = local;
    __syncthreads();
    for (int st = 128; st > 0; st >>= 1) {
        if (tid < st) sA[tid] += sA[tid + st];
        __syncthreads();
    }
    if (tid == 0) {
        float perplexity = expf(-sA[0]);
        float ploss = -logf(perplexity + 1e-10f);
        out[OFF_LOSS] = loss_vq + 0.01f * ploss;
        out[OFF_PERP] = perplexity;
    }
}

extern "C" void kernel_launch(void* const* d_in, const int* in_sizes, int n_in,
                              void* d_out, int out_size) {
    (void)in_sizes; (void)n_in; (void)out_size;
    const float* inp = (const float*)d_in[0];
    const float* cb  = (const float*)d_in[1];
    const float* gum = (const float*)d_in[2];
    float* out = (float*)d_out;

    vq_prep<<<K_EMB / 32, 256>>>(cb);
    vq_main<<<GRID_MAIN, THREADS_M>>>(inp, cb, gum, out);
    vq_final<<<1, 256>>>(out);
}